// round 14
// baseline (speedup 1.0000x reference)
#include <cuda_runtime.h>
#include <cuda_fp16.h>
#include <math.h>
#include <stdint.h>

// ---------------------------------------------------------------------------
// KAN feedforward, fp16 2-product split with slab reweighting (R13 math):
//   A1 = a_hi,  A2 = fp16(a_hi/c + c*a_lo),  c = 16;  out = (1-1/c^2)S1 + S2.
// R14: co-scheduled residual —
//   GEMM1 launch also runs prepW2 blocks (no sync needed),
//   GEMM2 launch runs L2-feature blocks pipelined per-mtile via flags.
// ---------------------------------------------------------------------------

#define D_MODEL 512
#define HIDDEN  1024
#define NFEAT   9
#define NTOK    4096
#define K1      (D_MODEL * NFEAT)   // 4608
#define K2      (HIDDEN  * NFEAT)   // 9216
#define CSPLIT  16.0f
#define W1FACT  0.99609375f         // 1 - 1/256

__device__ __half g_F  [(size_t)NTOK * 2 * K2];      // 151 MB (F1 then F2)
__device__ __half g_W1 [(size_t)HIDDEN * 2 * K1];    // 18.9 MB
__device__ __half g_W2 [(size_t)D_MODEL * 2 * K2];   // 18.9 MB
__device__ float  g_S1 [(size_t)4 * NTOK * HIDDEN];  // 67 MB GEMM1 slabs
__device__ float  g_S2 [(size_t)8 * NTOK * D_MODEL]; // 67 MB GEMM2 slabs
__device__ int    g_ctr[32];                         // per-mtile feat flags

// ---------------------------------------------------------------------------
// Helpers
// ---------------------------------------------------------------------------
__device__ __forceinline__ uint32_t smem_u32(const void* p) {
    uint32_t a;
    asm("{ .reg .u64 t; cvta.to.shared.u64 t, %1; cvt.u32.u64 %0, t; }"
        : "=r"(a) : "l"(p));
    return a;
}

__device__ __forceinline__ uint32_t lds_addr(uint32_t base, int row, int col16) {
    return base + row * 128 + ((col16 ^ (row & 7)) << 4);
}

#define CP_ASYNC16(sm, gm)                                                    \
    asm volatile("cp.async.cg.shared.global [%0], [%1], 16;"                  \
                 :: "r"(sm), "l"(gm) : "memory")
#define CP_COMMIT()  asm volatile("cp.async.commit_group;" ::: "memory")
#define CP_WAIT1()   asm volatile("cp.async.wait_group 1;" ::: "memory")

__device__ __forceinline__ void ldsm_x4(uint32_t r[4], uint32_t addr) {
    asm volatile("ldmatrix.sync.aligned.m8n8.x4.shared.b16 {%0,%1,%2,%3}, [%4];"
                 : "=r"(r[0]), "=r"(r[1]), "=r"(r[2]), "=r"(r[3]) : "r"(addr));
}

__device__ __forceinline__ void mma16816(float c[4], const uint32_t a[4],
                                         const uint32_t b[2]) {
    asm volatile(
        "mma.sync.aligned.m16n8k16.row.col.f32.f16.f16.f32 "
        "{%0,%1,%2,%3}, {%4,%5,%6,%7}, {%8,%9}, {%0,%1,%2,%3};"
        : "+f"(c[0]), "+f"(c[1]), "+f"(c[2]), "+f"(c[3])
        : "r"(a[0]), "r"(a[1]), "r"(a[2]), "r"(a[3]), "r"(b[0]), "r"(b[1]));
}

// ---------------------------------------------------------------------------
// Spline features (validated R3-R13)
// ---------------------------------------------------------------------------
__device__ __forceinline__ float knotf(int k) {
    return __fadd_rn(__fmul_rn((float)(k - 3), 0.4f), -1.0f);
}

__device__ __forceinline__ void kan_features(float x, float f[NFEAT]) {
    float sig = 1.0f / (1.0f + expf(-x));
    f[0] = x * sig;
#pragma unroll
    for (int g = 0; g < 8; g++) f[1 + g] = 0.0f;

    float u = (x - knotf(0)) * 2.5f;
    if (u > 16.0f) u = 16.0f;
    if (u < -16.0f) u = -16.0f;
    int j = (int)floorf(u);
    if (j < -1) j = -1;
    if (j > 11) j = 11;
    if (x < knotf(j))            j -= 1;
    else if (x >= knotf(j + 1))  j += 1;
    if (j < 0 || j > 10) return;

    float s  = (x - knotf(j)) * 2.5f;
    float s2 = s * s, s3 = s2 * s;
    float om = 1.0f - s;
    float w0 = om * om * om * (1.0f / 6.0f);
    float w1 = (3.0f * s3 - 6.0f * s2 + 4.0f) * (1.0f / 6.0f);
    float w2 = (-3.0f * s3 + 3.0f * s2 + 3.0f * s + 1.0f) * (1.0f / 6.0f);
    float w3 = s3 * (1.0f / 6.0f);
    float w[4] = {w0, w1, w2, w3};
    int g0 = j - 3;
#pragma unroll
    for (int r = 0; r < 4; r++) {
        int g = g0 + r;
        if (g >= 0 && g < 8) f[1 + g] = w[r];
    }
}

__device__ __forceinline__ void split2(float v, __half* hi, __half* x2) {
    __half h = __float2half(v);
    float hf = __half2float(h);
    float lo = v - hf;
    *hi = h;
    *x2 = __float2half(hf * (1.0f / CSPLIT) + lo * CSPLIT);
}

// ---------------------------------------------------------------------------
// pre_kernel (256 thr): featL1 (8192 blocks) + prepW1 (2048 blocks)
// ---------------------------------------------------------------------------
__device__ __forceinline__ void stage_copy256(
    const float f[NFEAT], int t, __half* sh, __half* s2,
    __half* dst_hi_base, int K) {
#pragma unroll
    for (int fi = 0; fi < NFEAT; fi++)
        split2(f[fi], &sh[t * NFEAT + fi], &s2[t * NFEAT + fi]);
    __syncthreads();
    const uint4* v1 = reinterpret_cast<const uint4*>(sh);
    const uint4* v2 = reinterpret_cast<const uint4*>(s2);
    uint4* dh = reinterpret_cast<uint4*>(dst_hi_base);
    uint4* d2 = reinterpret_cast<uint4*>(dst_hi_base + K);
    dh[t] = v1[t];
    d2[t] = v2[t];
    if (t < 32) {
        dh[256 + t] = v1[256 + t];
        d2[256 + t] = v2[256 + t];
    }
}

__global__ __launch_bounds__(256)
void pre_kernel(const float* __restrict__ X,
                const float* __restrict__ c1, const float* __restrict__ sb1,
                const float* __restrict__ sp1,
                __half* __restrict__ F1q, __half* __restrict__ W1q) {
    __shared__ __align__(16) __half sh[256 * NFEAT];
    __shared__ __align__(16) __half s2[256 * NFEAT];
    const int b = blockIdx.x;
    const int t = threadIdx.x;

    if (b < 2 * NTOK) {
        const int n  = b >> 1;
        const int i0 = (b & 1) << 8;
        float x = X[(size_t)n * D_MODEL + i0 + t];
        float f[NFEAT];
        kan_features(x, f);
        stage_copy256(f, t, sh, s2,
            F1q + (size_t)n * 2 * K1 + (size_t)i0 * NFEAT, K1);
    } else {
        const int bb = b - 2 * NTOK;
        const int o  = bb >> 1;
        const int i0 = (bb & 1) << 8;
        const int i  = i0 + t;
        size_t io = (size_t)i * HIDDEN + o;
        float sp = sp1[io];
        float w[NFEAT];
        w[0] = sb1[io];
        const float* c = c1 + io * 8;
#pragma unroll
        for (int g = 0; g < 8; g++) w[1 + g] = c[g] * sp;
        stage_copy256(w, t, sh, s2,
            W1q + (size_t)o * 2 * K1 + (size_t)i0 * NFEAT, K1);
    }
}

// ---------------------------------------------------------------------------
// GEMM body (R13 mainloop, blockIdx passed explicitly)
// ---------------------------------------------------------------------------
#define GEMM_BK      64
#define A_BYTES      (128 * 128)
#define STAGE_BYTES  (2 * A_BYTES)
#define SMEM_GEMM    (3 * STAGE_BYTES)

__device__ void gemm_body(const __half* __restrict__ A,
                          const __half* __restrict__ B,
                          float* __restrict__ C,
                          int nchunks, int PK, int ldc, size_t csplit,
                          int bx, int by, int bz, char* smem_raw) {
    const uint32_t sb = smem_u32(smem_raw);
    const int tid  = threadIdx.x;
    const int lane = tid & 31;
    const int wid  = tid >> 5;
    const int m0w  = (wid & 1) * 64;
    const int n0w  = (wid >> 1) * 64;
    const int m0   = by * 128;
    const int o0   = bx * 128;
    const int z0   = bz * nchunks;
    float* Cz      = C + (size_t)bz * csplit;

    const __half* Arow = A + (size_t)m0 * PK;
    const __half* Brow = B + (size_t)o0 * PK;

    const int r0   = tid >> 3;
    const int c16t = tid & 7;

    float acc[4][8][4];
#pragma unroll
    for (int mi = 0; mi < 4; mi++)
#pragma unroll
        for (int nj = 0; nj < 8; nj++)
#pragma unroll
            for (int e = 0; e < 4; e++) acc[mi][nj][e] = 0.0f;

    auto load_chunk = [&](int c, int s) {
        const uint32_t aB = sb + s * STAGE_BYTES;
        const uint32_t bB = aB + A_BYTES;
        const __half* Ap = Arow + (size_t)c * GEMM_BK + c16t * 8;
        const __half* Bp = Brow + (size_t)c * GEMM_BK + c16t * 8;
#pragma unroll
        for (int it = 0; it < 8; it++) {
            int row = r0 + it * 16;
            CP_ASYNC16(lds_addr(aB, row, c16t), Ap + (size_t)row * PK);
        }
#pragma unroll
        for (int it = 0; it < 8; it++) {
            int row = r0 + it * 16;
            CP_ASYNC16(lds_addr(bB, row, c16t), Bp + (size_t)row * PK);
        }
    };

    uint32_t fa[2][4][4], fb[2][4][4];
    auto load_frags = [&](uint32_t aB, uint32_t bB, int kk, int buf) {
#pragma unroll
        for (int mi = 0; mi < 4; mi++)
            ldsm_x4(fa[buf][mi], lds_addr(aB, m0w + mi * 16 + (lane & 15),
                                          kk * 2 + (lane >> 4)));
#pragma unroll
        for (int nj2 = 0; nj2 < 4; nj2++) {
            int rowB = n0w + nj2 * 16 + ((lane >> 4) << 3) + (lane & 7);
            int colB = kk * 2 + ((lane >> 3) & 1);
            ldsm_x4(fb[buf][nj2], lds_addr(bB, rowB, colB));
        }
    };

    load_chunk(z0 + 0, 0); CP_COMMIT();
    load_chunk(z0 + 1, 1); CP_COMMIT();

    for (int cc = 0; cc < nchunks; cc++) {
        CP_WAIT1();
        __syncthreads();
        if (cc + 2 < nchunks) load_chunk(z0 + cc + 2, (cc + 2) % 3);
        CP_COMMIT();

        const uint32_t aB = sb + (cc % 3) * STAGE_BYTES;
        const uint32_t bB = aB + A_BYTES;
        load_frags(aB, bB, 0, 0);
#pragma unroll
        for (int kk = 0; kk < 4; kk++) {
            const int cur = kk & 1;
            if (kk < 3) load_frags(aB, bB, kk + 1, cur ^ 1);
#pragma unroll
            for (int mi = 0; mi < 4; mi++)
#pragma unroll
                for (int nj = 0; nj < 8; nj++)
                    mma16816(acc[mi][nj], fa[cur][mi], &fb[cur][nj >> 1][(nj & 1) * 2]);
        }
    }

    const int g   = lane >> 2;
    const int cc0 = (lane & 3) * 2;
#pragma unroll
    for (int mi = 0; mi < 4; mi++) {
#pragma unroll
        for (int nj = 0; nj < 8; nj++) {
            int row = m0 + m0w + mi * 16 + g;
            int col = o0 + n0w + nj * 8 + cc0;
            float2 v0 = make_float2(acc[mi][nj][0], acc[mi][nj][1]);
            float2 v1 = make_float2(acc[mi][nj][2], acc[mi][nj][3]);
            *reinterpret_cast<float2*>(&Cz[(size_t)row * ldc + col]) = v0;
            *reinterpret_cast<float2*>(&Cz[(size_t)(row + 8) * ldc + col]) = v1;
        }
    }
}

// 8-value-per-thread stage + copy-out (128 thr): one full K-run per block.
// smem: sh = 9216 half (18 KB), s2 = sh + 9216.
__device__ __forceinline__ void stage_copy128x8(
    const float xs[8], int t, __half* sh, __half* s2,
    __half* dst_hi_base, int K) {
#pragma unroll
    for (int v = 0; v < 8; v++) {
        float f[NFEAT];
        kan_features(xs[v], f);
        int base = (v * 128 + t) * NFEAT;
#pragma unroll
        for (int fi = 0; fi < NFEAT; fi++)
            split2(f[fi], &sh[base + fi], &s2[base + fi]);
    }
    __syncthreads();
    const uint4* v1 = reinterpret_cast<const uint4*>(sh);
    const uint4* v2 = reinterpret_cast<const uint4*>(s2);
    uint4* dh = reinterpret_cast<uint4*>(dst_hi_base);
    uint4* d2 = reinterpret_cast<uint4*>(dst_hi_base + K);
#pragma unroll
    for (int p = t; p < 1152; p += 128) {   // K2/8 = 1152 uint4 per buffer
        dh[p] = v1[p];
        d2[p] = v2[p];
    }
}

// ---------------------------------------------------------------------------
// Merged GEMM1 launch: 32 groups x [32 GEMM CTAs | 16 prepW2 blocks] = 1536.
// prepW2 has no intra-kernel consumer (W2 read by next launch) -> no sync.
// ---------------------------------------------------------------------------
__global__ __launch_bounds__(128, 2)
void gemm1_merged(const __half* __restrict__ A, const __half* __restrict__ B,
                  float* __restrict__ C,
                  const float* __restrict__ c2, const float* __restrict__ sb2,
                  const float* __restrict__ sp2, __half* __restrict__ W2q) {
    extern __shared__ __align__(1024) char smem_raw[];
    const int grp = blockIdx.x / 48;
    const int r   = blockIdx.x - grp * 48;
    const int t   = threadIdx.x;

    if (r < 32) {
        // GEMM1 CTA: x in [0,8), z in [0,4), y = grp
        gemm_body(A, B, C, (2 * K1 / GEMM_BK) / 4, 2 * K1, HIDDEN,
                  (size_t)NTOK * HIDDEN, r & 7, grp, r >> 3, smem_raw);
    } else {
        // prepW2: o = grp*16 + (r-32), 8 i-values per thread
        const int o = grp * 16 + (r - 32);
        float xsw[8][NFEAT];
        float xs[8];
#pragma unroll
        for (int v = 0; v < 8; v++) {
            int i = v * 128 + t;
            size_t io = (size_t)i * D_MODEL + o;
            float sp = sp2[io];
            xsw[v][0] = sb2[io];
            const float* c = c2 + io * 8;
#pragma unroll
            for (int g = 0; g < 8; g++) xsw[v][1 + g] = c[g] * sp;
        }
        __half* sh = reinterpret_cast<__half*>(smem_raw);
        __half* s2h = sh + 9216;
        // stage all 8 values (inline, same as stage_copy128x8 but with w-arrays)
#pragma unroll
        for (int v = 0; v < 8; v++) {
            int base = (v * 128 + t) * NFEAT;
#pragma unroll
            for (int fi = 0; fi < NFEAT; fi++)
                split2(xsw[v][fi], &sh[base + fi], &s2h[base + fi]);
        }
        __syncthreads();
        const uint4* v1 = reinterpret_cast<const uint4*>(sh);
        const uint4* v2 = reinterpret_cast<const uint4*>(s2h);
        uint4* dh = reinterpret_cast<uint4*>(W2q + (size_t)o * 2 * K2);
        uint4* d2 = dh + (K2 / 8);
#pragma unroll
        for (int p = t; p < 1152; p += 128) {
            dh[p] = v1[p];
            d2[p] = v2[p];
        }
        (void)xs;
    }
}

// ---------------------------------------------------------------------------
// Merged GEMM2 launch: 32 groups x [128 feat blocks | 32 GEMM CTAs] = 5120.
// feat block: 1 token, 8 dims/thread; sets g_ctr[mtile].
// GEMM CTA (y) spin-waits g_ctr[y] == 128 before touching A.
// ---------------------------------------------------------------------------
__global__ __launch_bounds__(128, 2)
void gemm2_merged(const float* __restrict__ S1, size_t stride,
                  __half* __restrict__ Fq,
                  const __half* __restrict__ B, float* __restrict__ C) {
    extern __shared__ __align__(1024) char smem_raw[];
    const int grp = blockIdx.x / 160;
    const int r   = blockIdx.x - grp * 160;
    const int t   = threadIdx.x;

    if (r < 128) {
        // feat: token = grp*128 + r
        const int tok = grp * 128 + r;
        float xs[8];
        size_t base = (size_t)tok * HIDDEN + t;
#pragma unroll
        for (int v = 0; v < 8; v++) {
            size_t idx = base + v * 128;
            xs[v] = (S1[idx] + S1[idx + stride]) * W1FACT
                  + (S1[idx + 2 * stride] + S1[idx + 3 * stride]);
        }
        __half* sh = reinterpret_cast<__half*>(smem_raw);
        __half* s2h = sh + 9216;
        stage_copy128x8(xs, t, sh, s2h, Fq + (size_t)tok * 2 * K2, K2);
        __threadfence();
        __syncthreads();
        if (t == 0) atomicAdd(&g_ctr[grp], 1);
    } else {
        // GEMM2 CTA: q = r-128: x in [0,4), z in [0,8), y = grp
        const int q = r - 128;
        if (t == 0) {
            while (*(volatile int*)&g_ctr[grp] < 128)
                asm volatile("nanosleep.u32 64;");
            __threadfence();
        }
        __syncthreads();
        gemm_body(Fq, B, C, (2 * K2 / GEMM_BK) / 8, 2 * K2, D_MODEL,
                  (size_t)NTOK * D_MODEL, q & 3, grp, q >> 2, smem_raw);
    }
}

// ---------------------------------------------------------------------------
// Final reweighted reduction + flag reset for next graph replay
// ---------------------------------------------------------------------------
__global__ void add_splits8w(const float* __restrict__ s, float* __restrict__ out,
                             size_t stride, int n4) {
    if (blockIdx.x == 0 && threadIdx.x < 32) g_ctr[threadIdx.x] = 0;
    int i = blockIdx.x * blockDim.x + threadIdx.x;
    if (i >= n4) return;
    float4 a = reinterpret_cast<const float4*>(s)[i];
#pragma unroll
    for (int z = 1; z < 4; z++) {
        float4 b = reinterpret_cast<const float4*>(s + z * stride)[i];
        a.x += b.x; a.y += b.y; a.z += b.z; a.w += b.w;
    }
    a.x *= W1FACT; a.y *= W1FACT; a.z *= W1FACT; a.w *= W1FACT;
#pragma unroll
    for (int z = 4; z < 8; z++) {
        float4 b = reinterpret_cast<const float4*>(s + z * stride)[i];
        a.x += b.x; a.y += b.y; a.z += b.z; a.w += b.w;
    }
    *reinterpret_cast<float4*>(out + (size_t)i * 4) = a;
}

// ---------------------------------------------------------------------------
// Launch (4 kernels)
// ---------------------------------------------------------------------------
extern "C" void kernel_launch(void* const* d_in, const int* in_sizes, int n_in,
                              void* d_out, int out_size) {
    const float* x   = (const float*)d_in[0];
    const float* c1  = (const float*)d_in[1];
    const float* sb1 = (const float*)d_in[2];
    const float* sp1 = (const float*)d_in[3];
    const float* c2  = (const float*)d_in[4];
    const float* sb2 = (const float*)d_in[5];
    const float* sp2 = (const float*)d_in[6];
    float* out = (float*)d_out;

    const int D = D_MODEL, H = HIDDEN;
    const int N = in_sizes[0] / D;   // 4096

    void *pF, *pW1, *pW2, *pS1, *pS2;
    cudaGetSymbolAddress(&pF,  g_F);
    cudaGetSymbolAddress(&pW1, g_W1);
    cudaGetSymbolAddress(&pW2, g_W2);
    cudaGetSymbolAddress(&pS1, g_S1);
    cudaGetSymbolAddress(&pS2, g_S2);
    __half* Fq  = (__half*)pF;
    __half* W1q = (__half*)pW1;
    __half* W2q = (__half*)pW2;
    float* S1 = (float*)pS1;
    float* S2 = (float*)pS2;

    static bool attr_set = false;
    if (!attr_set) {
        cudaFuncSetAttribute(gemm1_merged,
                             cudaFuncAttributeMaxDynamicSharedMemorySize, SMEM_GEMM);
        cudaFuncSetAttribute(gemm2_merged,
                             cudaFuncAttributeMaxDynamicSharedMemorySize, SMEM_GEMM);
        attr_set = true;
    }

    // 1) featL1 + prepW1
    pre_kernel<<<2 * N + 2 * H, 256>>>(x, c1, sb1, sp1, Fq, W1q);

    // 2) GEMM1 (split-K4, 1024 CTAs) + co-run prepW2 (512 blocks)
    gemm1_merged<<<32 * 48, 128, SMEM_GEMM>>>(Fq, W1q, S1, c2, sb2, sp2, W2q);

    // 3) GEMM2 (split-K8, 1024 CTAs) + pipelined L2 features (4096 blocks)
    gemm2_merged<<<32 * 160, 128, SMEM_GEMM>>>(S1, (size_t)N * H, Fq, W2q, S2);

    // 4) Final reweighted reduction (+ flag reset for next replay)
    add_splits8w<<<(N * D / 4 + 255) / 256, 256>>>(S2, out, (size_t)N * D, N * D / 4);
}

// round 15
// speedup vs baseline: 1.2209x; 1.2209x over previous
#include <cuda_runtime.h>
#include <cuda_fp16.h>
#include <math.h>
#include <stdint.h>

// ---------------------------------------------------------------------------
// KAN feedforward, fp16 2-product split with slab reweighting (R13 math):
//   A1 = a_hi,  A2 = fp16(a_hi/c + c*a_lo),  c = 16
//   S1 = A1.B1;  S2 = A2.B2;  out = (1 - 1/c^2)*S1 + S2
//   (exact hi.hi cancellation via separate split-K slabs; Keff = 2K)
// R15: R13 pipeline, with prepW2 moved to a forked stream branch so it
//   overlaps pre_kernel + GEMM1 at its own (high) occupancy. Join before
//   GEMM2. All arithmetic byte-identical to R13.
// ---------------------------------------------------------------------------

#define D_MODEL 512
#define HIDDEN  1024
#define NFEAT   9
#define NTOK    4096
#define K1      (D_MODEL * NFEAT)   // 4608
#define K2      (HIDDEN  * NFEAT)   // 9216
#define CSPLIT  16.0f
#define W1FACT  0.99609375f         // 1 - 1/256, exact in fp32

__device__ __half g_F  [(size_t)NTOK * 2 * K2];     // 151 MB (both layers)
__device__ __half g_W1 [(size_t)HIDDEN * 2 * K1];   // 18.9 MB
__device__ __half g_W2 [(size_t)D_MODEL * 2 * K2];  // 18.9 MB
__device__ float  g_Sd [(size_t)8 * NTOK * D_MODEL];// 67 MB slabs (4xNH == 8xND)

// ---------------------------------------------------------------------------
// Helpers
// ---------------------------------------------------------------------------
__device__ __forceinline__ uint32_t smem_u32(const void* p) {
    uint32_t a;
    asm("{ .reg .u64 t; cvta.to.shared.u64 t, %1; cvt.u32.u64 %0, t; }"
        : "=r"(a) : "l"(p));
    return a;
}

__device__ __forceinline__ uint32_t lds_addr(uint32_t base, int row, int col16) {
    return base + row * 128 + ((col16 ^ (row & 7)) << 4);
}

#define CP_ASYNC16(sm, gm)                                                    \
    asm volatile("cp.async.cg.shared.global [%0], [%1], 16;"                  \
                 :: "r"(sm), "l"(gm) : "memory")
#define CP_COMMIT()  asm volatile("cp.async.commit_group;" ::: "memory")
#define CP_WAIT1()   asm volatile("cp.async.wait_group 1;" ::: "memory")

__device__ __forceinline__ void ldsm_x4(uint32_t r[4], uint32_t addr) {
    asm volatile("ldmatrix.sync.aligned.m8n8.x4.shared.b16 {%0,%1,%2,%3}, [%4];"
                 : "=r"(r[0]), "=r"(r[1]), "=r"(r[2]), "=r"(r[3]) : "r"(addr));
}

__device__ __forceinline__ void mma16816(float c[4], const uint32_t a[4],
                                         const uint32_t b[2]) {
    asm volatile(
        "mma.sync.aligned.m16n8k16.row.col.f32.f16.f16.f32 "
        "{%0,%1,%2,%3}, {%4,%5,%6,%7}, {%8,%9}, {%0,%1,%2,%3};"
        : "+f"(c[0]), "+f"(c[1]), "+f"(c[2]), "+f"(c[3])
        : "r"(a[0]), "r"(a[1]), "r"(a[2]), "r"(a[3]), "r"(b[0]), "r"(b[1]));
}

// ---------------------------------------------------------------------------
// Spline features (validated R3-R13)
// ---------------------------------------------------------------------------
__device__ __forceinline__ float knotf(int k) {
    return __fadd_rn(__fmul_rn((float)(k - 3), 0.4f), -1.0f);
}

__device__ __forceinline__ void kan_features(float x, float f[NFEAT]) {
    float sig = 1.0f / (1.0f + expf(-x));
    f[0] = x * sig;
#pragma unroll
    for (int g = 0; g < 8; g++) f[1 + g] = 0.0f;

    float u = (x - knotf(0)) * 2.5f;
    if (u > 16.0f) u = 16.0f;
    if (u < -16.0f) u = -16.0f;
    int j = (int)floorf(u);
    if (j < -1) j = -1;
    if (j > 11) j = 11;
    if (x < knotf(j))            j -= 1;
    else if (x >= knotf(j + 1))  j += 1;
    if (j < 0 || j > 10) return;

    float s  = (x - knotf(j)) * 2.5f;
    float s2 = s * s, s3 = s2 * s;
    float om = 1.0f - s;
    float w0 = om * om * om * (1.0f / 6.0f);
    float w1 = (3.0f * s3 - 6.0f * s2 + 4.0f) * (1.0f / 6.0f);
    float w2 = (-3.0f * s3 + 3.0f * s2 + 3.0f * s + 1.0f) * (1.0f / 6.0f);
    float w3 = s3 * (1.0f / 6.0f);
    float w[4] = {w0, w1, w2, w3};
    int g0 = j - 3;
#pragma unroll
    for (int r = 0; r < 4; r++) {
        int g = g0 + r;
        if (g >= 0 && g < 8) f[1 + g] = w[r];
    }
}

// v -> (hi, X2 = fp16(hi/c + c*lo)); stage in smem; 128-bit copy-out.
__device__ __forceinline__ void split_stage_copyout(
    const float f[NFEAT], int t, __half* sh, __half* s2,
    __half* dst_hi_base, int K) {
#pragma unroll
    for (int fi = 0; fi < NFEAT; fi++) {
        __half h = __float2half(f[fi]);
        float hf = __half2float(h);
        float lo = f[fi] - hf;
        sh[t * NFEAT + fi] = h;
        s2[t * NFEAT + fi] = __float2half(hf * (1.0f / CSPLIT) + lo * CSPLIT);
    }
    __syncthreads();
    const uint4* v1 = reinterpret_cast<const uint4*>(sh);
    const uint4* v2 = reinterpret_cast<const uint4*>(s2);
    uint4* dh = reinterpret_cast<uint4*>(dst_hi_base);
    uint4* d2 = reinterpret_cast<uint4*>(dst_hi_base + K);
    dh[t] = v1[t];
    d2[t] = v2[t];
    if (t < 32) {
        dh[256 + t] = v1[256 + t];
        d2[256 + t] = v2[256 + t];
    }
}

// ---------------------------------------------------------------------------
// pre_kernel: featL1 (8192 blocks) + prepW1 (2048 blocks)  [main stream]
// ---------------------------------------------------------------------------
__global__ __launch_bounds__(256)
void pre_kernel(const float* __restrict__ X,
                const float* __restrict__ c1, const float* __restrict__ sb1,
                const float* __restrict__ sp1,
                __half* __restrict__ F1q, __half* __restrict__ W1q) {
    __shared__ __align__(16) __half sh[256 * NFEAT];
    __shared__ __align__(16) __half s2[256 * NFEAT];
    const int b = blockIdx.x;
    const int t = threadIdx.x;

    if (b < 2 * NTOK) {
        const int n  = b >> 1;
        const int i0 = (b & 1) << 8;
        float x = X[(size_t)n * D_MODEL + i0 + t];
        float f[NFEAT];
        kan_features(x, f);
        split_stage_copyout(f, t, sh, s2,
            F1q + (size_t)n * 2 * K1 + (size_t)i0 * NFEAT, K1);
    } else {
        const int bb = b - 2 * NTOK;
        const int o  = bb >> 1;
        const int i0 = (bb & 1) << 8;
        const int i  = i0 + t;
        size_t io = (size_t)i * HIDDEN + o;
        float sp = sp1[io];
        float w[NFEAT];
        w[0] = sb1[io];
        const float* c = c1 + io * 8;
#pragma unroll
        for (int g = 0; g < 8; g++) w[1 + g] = c[g] * sp;
        split_stage_copyout(w, t, sh, s2,
            W1q + (size_t)o * 2 * K1 + (size_t)i0 * NFEAT, K1);
    }
}

// ---------------------------------------------------------------------------
// prepW2 (2048 blocks)  [forked aux stream: overlaps pre_kernel + GEMM1;
// depends only on raw inputs, consumed only by GEMM2 after the join]
// ---------------------------------------------------------------------------
__global__ __launch_bounds__(256)
void prep_w2(const float* __restrict__ c2, const float* __restrict__ sb2,
             const float* __restrict__ sp2, __half* __restrict__ W2q) {
    __shared__ __align__(16) __half sh[256 * NFEAT];
    __shared__ __align__(16) __half s2[256 * NFEAT];
    const int bb = blockIdx.x;
    const int o  = bb >> 2;
    const int i0 = (bb & 3) << 8;
    const int t  = threadIdx.x;
    const int i  = i0 + t;

    size_t io = (size_t)i * D_MODEL + o;
    float sp = sp2[io];
    float w[NFEAT];
    w[0] = sb2[io];
    const float* c = c2 + io * 8;
#pragma unroll
    for (int g = 0; g < 8; g++) w[1 + g] = c[g] * sp;
    split_stage_copyout(w, t, sh, s2,
        W2q + (size_t)o * 2 * K2 + (size_t)i0 * NFEAT, K2);
}

// ---------------------------------------------------------------------------
// Fused L2 features: h = (S0+S1)*(1-1/c^2) + (S2+S3), features + split.
// ---------------------------------------------------------------------------
__global__ __launch_bounds__(256)
void build_features_sum4(const float* __restrict__ S, size_t stride,
                         __half* __restrict__ Fq) {
    __shared__ __align__(16) __half sh[256 * NFEAT];
    __shared__ __align__(16) __half s2[256 * NFEAT];
    const int n  = blockIdx.x;
    const int i0 = blockIdx.y << 8;
    const int t  = threadIdx.x;

    size_t idx = (size_t)n * HIDDEN + i0 + t;
    float x = (S[idx] + S[idx + stride]) * W1FACT
            + (S[idx + 2 * stride] + S[idx + 3 * stride]);

    float f[NFEAT];
    kan_features(x, f);
    split_stage_copyout(f, t, sh, s2,
        Fq + (size_t)n * 2 * K2 + (size_t)i0 * NFEAT, K2);
}

// ---------------------------------------------------------------------------
// GEMM (R7-R13 mainloop; at the rt=12 HMMA pipe floor)
// ---------------------------------------------------------------------------
#define GEMM_BK      64
#define A_BYTES      (128 * 128)
#define STAGE_BYTES  (2 * A_BYTES)
#define SMEM_GEMM    (3 * STAGE_BYTES)

__global__ __launch_bounds__(128, 2)
void kan_gemm_mma(const __half* __restrict__ A,
                  const __half* __restrict__ B,
                  float* __restrict__ C,
                  int nchunks, int PK, int ldc, size_t csplit) {
    extern __shared__ __align__(1024) char smem_raw[];
    const uint32_t sb = smem_u32(smem_raw);

    const int tid  = threadIdx.x;
    const int lane = tid & 31;
    const int wid  = tid >> 5;
    const int m0w  = (wid & 1) * 64;
    const int n0w  = (wid >> 1) * 64;
    const int m0   = blockIdx.y * 128;
    const int o0   = blockIdx.x * 128;
    const int z0   = blockIdx.z * nchunks;
    float* Cz      = C + (size_t)blockIdx.z * csplit;

    const __half* Arow = A + (size_t)m0 * PK;
    const __half* Brow = B + (size_t)o0 * PK;

    const int r0   = tid >> 3;
    const int c16t = tid & 7;

    float acc[4][8][4];
#pragma unroll
    for (int mi = 0; mi < 4; mi++)
#pragma unroll
        for (int nj = 0; nj < 8; nj++)
#pragma unroll
            for (int e = 0; e < 4; e++) acc[mi][nj][e] = 0.0f;

    auto load_chunk = [&](int c, int s) {
        const uint32_t aB = sb + s * STAGE_BYTES;
        const uint32_t bB = aB + A_BYTES;
        const __half* Ap = Arow + (size_t)c * GEMM_BK + c16t * 8;
        const __half* Bp = Brow + (size_t)c * GEMM_BK + c16t * 8;
#pragma unroll
        for (int it = 0; it < 8; it++) {
            int row = r0 + it * 16;
            CP_ASYNC16(lds_addr(aB, row, c16t), Ap + (size_t)row * PK);
        }
#pragma unroll
        for (int it = 0; it < 8; it++) {
            int row = r0 + it * 16;
            CP_ASYNC16(lds_addr(bB, row, c16t), Bp + (size_t)row * PK);
        }
    };

    uint32_t fa[2][4][4], fb[2][4][4];
    auto load_frags = [&](uint32_t aB, uint32_t bB, int kk, int buf) {
#pragma unroll
        for (int mi = 0; mi < 4; mi++)
            ldsm_x4(fa[buf][mi], lds_addr(aB, m0w + mi * 16 + (lane & 15),
                                          kk * 2 + (lane >> 4)));
#pragma unroll
        for (int nj2 = 0; nj2 < 4; nj2++) {
            int rowB = n0w + nj2 * 16 + ((lane >> 4) << 3) + (lane & 7);
            int colB = kk * 2 + ((lane >> 3) & 1);
            ldsm_x4(fb[buf][nj2], lds_addr(bB, rowB, colB));
        }
    };

    load_chunk(z0 + 0, 0); CP_COMMIT();
    load_chunk(z0 + 1, 1); CP_COMMIT();

    for (int cc = 0; cc < nchunks; cc++) {
        CP_WAIT1();
        __syncthreads();
        if (cc + 2 < nchunks) load_chunk(z0 + cc + 2, (cc + 2) % 3);
        CP_COMMIT();

        const uint32_t aB = sb + (cc % 3) * STAGE_BYTES;
        const uint32_t bB = aB + A_BYTES;
        load_frags(aB, bB, 0, 0);
#pragma unroll
        for (int kk = 0; kk < 4; kk++) {
            const int cur = kk & 1;
            if (kk < 3) load_frags(aB, bB, kk + 1, cur ^ 1);
#pragma unroll
            for (int mi = 0; mi < 4; mi++)
#pragma unroll
                for (int nj = 0; nj < 8; nj++)
                    mma16816(acc[mi][nj], fa[cur][mi], &fb[cur][nj >> 1][(nj & 1) * 2]);
        }
    }

    const int g   = lane >> 2;
    const int cc0 = (lane & 3) * 2;
#pragma unroll
    for (int mi = 0; mi < 4; mi++) {
#pragma unroll
        for (int nj = 0; nj < 8; nj++) {
            int row = m0 + m0w + mi * 16 + g;
            int col = o0 + n0w + nj * 8 + cc0;
            float2 v0 = make_float2(acc[mi][nj][0], acc[mi][nj][1]);
            float2 v1 = make_float2(acc[mi][nj][2], acc[mi][nj][3]);
            *reinterpret_cast<float2*>(&Cz[(size_t)row * ldc + col]) = v0;
            *reinterpret_cast<float2*>(&Cz[(size_t)(row + 8) * ldc + col]) = v1;
        }
    }
}

// ---------------------------------------------------------------------------
// Final reduction with term reweighting:
//   out = (S0+S1+S2+S3)*(1-1/c^2) + (S4+S5+S6+S7)
// ---------------------------------------------------------------------------
__global__ void add_splits8w(const float* __restrict__ s, float* __restrict__ out,
                             size_t stride, int n4) {
    int i = blockIdx.x * blockDim.x + threadIdx.x;
    if (i >= n4) return;
    float4 a = reinterpret_cast<const float4*>(s)[i];
#pragma unroll
    for (int z = 1; z < 4; z++) {
        float4 b = reinterpret_cast<const float4*>(s + z * stride)[i];
        a.x += b.x; a.y += b.y; a.z += b.z; a.w += b.w;
    }
    a.x *= W1FACT; a.y *= W1FACT; a.z *= W1FACT; a.w *= W1FACT;
#pragma unroll
    for (int z = 4; z < 8; z++) {
        float4 b = reinterpret_cast<const float4*>(s + z * stride)[i];
        a.x += b.x; a.y += b.y; a.z += b.z; a.w += b.w;
    }
    *reinterpret_cast<float4*>(out + (size_t)i * 4) = a;
}

// ---------------------------------------------------------------------------
// Launch: fork prepW2 onto an aux stream (overlaps pre_kernel + GEMM1),
// join before GEMM2. All kernels/launch shapes otherwise identical to R13.
// ---------------------------------------------------------------------------
extern "C" void kernel_launch(void* const* d_in, const int* in_sizes, int n_in,
                              void* d_out, int out_size) {
    const float* x   = (const float*)d_in[0];
    const float* c1  = (const float*)d_in[1];
    const float* sb1 = (const float*)d_in[2];
    const float* sp1 = (const float*)d_in[3];
    const float* c2  = (const float*)d_in[4];
    const float* sb2 = (const float*)d_in[5];
    const float* sp2 = (const float*)d_in[6];
    float* out = (float*)d_out;

    const int D = D_MODEL, H = HIDDEN;
    const int N = in_sizes[0] / D;   // 4096

    void *pF, *pW1, *pW2, *pS;
    cudaGetSymbolAddress(&pF,  g_F);
    cudaGetSymbolAddress(&pW1, g_W1);
    cudaGetSymbolAddress(&pW2, g_W2);
    cudaGetSymbolAddress(&pS,  g_Sd);
    __half* Fq  = (__half*)pF;
    __half* W1q = (__half*)pW1;
    __half* W2q = (__half*)pW2;
    float* S = (float*)pS;

    static cudaStream_t sAux = nullptr;
    static cudaEvent_t evFork = nullptr, evJoin = nullptr;
    static bool attr_set = false;
    if (!attr_set) {
        cudaFuncSetAttribute(kan_gemm_mma,
                             cudaFuncAttributeMaxDynamicSharedMemorySize, SMEM_GEMM);
        cudaStreamCreateWithFlags(&sAux, cudaStreamNonBlocking);
        cudaEventCreateWithFlags(&evFork, cudaEventDisableTiming);
        cudaEventCreateWithFlags(&evJoin, cudaEventDisableTiming);
        attr_set = true;
    }

    // Fork: aux branch starts at the capture head and runs prepW2
    // (depends only on raw inputs; consumed only by GEMM2 after the join).
    cudaEventRecord(evFork, 0);
    cudaStreamWaitEvent(sAux, evFork, 0);
    prep_w2<<<4 * D, 256, 0, sAux>>>(c2, sb2, sp2, W2q);
    cudaEventRecord(evJoin, sAux);

    // Main branch: featL1 + prepW1, then GEMM1
    pre_kernel<<<2 * N + 2 * H, 256>>>(x, c1, sb1, sp1, Fq, W1q);
    kan_gemm_mma<<<dim3(H / 128, N / 128, 4), 128, SMEM_GEMM>>>(
        Fq, W1q, S, (2 * K1 / 64) / 4, 2 * K1, H, (size_t)N * H);

    // L2 features fused with reweighted 4-slab sum
    build_features_sum4<<<dim3(N, H / 256), 256>>>(S, (size_t)N * H, Fq);

    // Join: W2 must be complete before GEMM2
    cudaStreamWaitEvent(0, evJoin, 0);
    kan_gemm_mma<<<dim3(D / 128, N / 128, 8), 128, SMEM_GEMM>>>(
        Fq, W2q, S, (2 * K2 / 64) / 8, 2 * K2, D, (size_t)N * D);

    // Final reweighted fixed-order reduction
    add_splits8w<<<(N * D / 4 + 255) / 256, 256>>>(S, out, (size_t)N * D, N * D / 4);
}